// round 1
// baseline (speedup 1.0000x reference)
#include <cuda_runtime.h>
#include <math.h>

// Problem constants
#define Bb 4
#define Nn 128
#define Kk 250
#define Ss 250
#define Mm 32
#define NSEQ 1000        // sequences per path (B*S or B*K)
#define LSEQ 250         // sequence length per path
#define SEQ_STRIDE 32000 // Nn*LSEQ
#define TOT 32000000     // B*N*K*S
#define PER_B 8000000    // N*K*S
#define NM 4096          // Nn*Mm

// -------- device scratch (static allocation only; no cudaMalloc allowed) ------
__device__ float g_uT[TOT];   // intra-path u in [seq][h][l] layout
__device__ float g_y[TOT];    // post-conv+gelu [seq][h][l]
__device__ float g_g[TOT];    // post-GLU      [seq][h][l]
__device__ float g_b2[TOT];   // post-lw       [seq][n][l]
__device__ float g_X1[TOT];   // intra result  [B][N][K][S]
__device__ float g_P[2 * 4 * NM]; // per path: a_re, a_im, c_re, c_im  [h][m]
__device__ float g_red[Bb * 128 * 2];
__device__ float g_stats[Bb * 2];

// ---------------- parameter prep: a = exp(dt*A), C' = 2*C*(a-1)/A ------------
__global__ void prep_params(const float* __restrict__ log_dt,
                            const float* __restrict__ logA_re,
                            const float* __restrict__ A_im,
                            const float* __restrict__ C_re,
                            const float* __restrict__ C_im,
                            int path)
{
    int h = blockIdx.x;
    int m = threadIdx.x;
    float dt  = expf(log_dt[h]);
    float Are = -expf(logA_re[h * Mm + m]);
    float Aim = A_im[h * Mm + m];
    float dre = dt * Are, dim = dt * Aim;
    float e   = expf(dre);
    float are = e * cosf(dim);
    float aim = e * sinf(dim);
    // (a-1)/A  via conj
    float nre = are - 1.0f, nim = aim;
    float d2  = Are * Are + Aim * Aim;
    float qre = (nre * Are + nim * Aim) / d2;
    float qim = (nim * Are - nre * Aim) / d2;
    float cr  = C_re[h * Mm + m], ci = C_im[h * Mm + m];
    float c2r = 2.0f * (cr * qre - ci * qim);
    float c2i = 2.0f * (cr * qim + ci * qre);
    int base = path * 4 * NM + h * Mm + m;
    g_P[base + 0 * NM] = are;
    g_P[base + 1 * NM] = aim;
    g_P[base + 2 * NM] = c2r;
    g_P[base + 3 * NM] = c2i;
}

// -------- transpose x [B,N,K,S] -> g_uT [(b*S+s)][h][k] (intra u layout) -----
__global__ void transpose_in(const float* __restrict__ x)
{
    __shared__ float tile[32][33];
    int bh = blockIdx.x;            // b*128 + h
    int b = bh >> 7, h = bh & 127;
    int k0 = blockIdx.y * 32, s0 = blockIdx.z * 32;
    int tx = threadIdx.x, ty = threadIdx.y;
    const float* xin = x + ((b * 128 + h) * 250) * 250;
    #pragma unroll
    for (int yy = 0; yy < 32; yy += 8) {
        int k = k0 + ty + yy, s = s0 + tx;
        if (k < 250 && s < 250)
            tile[ty + yy][tx] = xin[k * 250 + s];
    }
    __syncthreads();
    #pragma unroll
    for (int yy = 0; yy < 32; yy += 8) {
        int s = s0 + ty + yy, k = k0 + tx;
        if (k < 250 && s < 250)
            g_uT[(b * 250 + s) * SEQ_STRIDE + h * 250 + k] = tile[tx][ty + yy];
    }
}

// ------------- S4D conv as complex mode recurrence + D*u + GELU --------------
// block: 128 threads = 32 (seq,h) groups of 4 lanes; 8 modes per lane.
__global__ void conv_s4(int path, const float* __restrict__ Dv)
{
    __shared__ float u_sm[32][250];
    __shared__ float y_sm[32][32];
    int seq = blockIdx.x;
    int h0  = blockIdx.y * 32;
    int tid = threadIdx.x;

    const float* src;
    int base, s_h;
    if (path == 0) { // intra: g_uT contiguous [seq][h][l]
        src = g_uT;
        base = seq * SEQ_STRIDE;
        s_h = 250;
    } else {         // inter: g_X1 [B][N][K][S], seq=(b,k), l=s
        src = g_X1;
        int b = seq / 250, k = seq - b * 250;
        base = b * PER_B + k * 250;
        s_h = 62500;
    }

    for (int idx = tid; idx < 32 * 250; idx += 128) {
        int h = idx / 250, l = idx - h * 250;
        u_sm[h][l] = src[base + (h0 + h) * s_h + l];
    }
    __syncthreads();

    int g = tid >> 2, r = tid & 3;
    int pb = path * 4 * NM + (h0 + g) * Mm + r * 8;
    float are[8], aim[8], cre[8], cim[8], sre[8], sim[8];
    #pragma unroll
    for (int i = 0; i < 8; i++) {
        are[i] = g_P[pb + i];
        aim[i] = g_P[pb + NM + i];
        cre[i] = g_P[pb + 2 * NM + i];
        cim[i] = g_P[pb + 3 * NM + i];
        sre[i] = 0.f; sim[i] = 0.f;
    }

    int ybase = seq * SEQ_STRIDE + h0 * 250;
    for (int l0 = 0; l0 < 250; l0 += 32) {
        int lend = min(l0 + 32, 250);
        for (int l = l0; l < lend; l++) {
            float u = u_sm[g][l];
            float acc = 0.f;
            #pragma unroll
            for (int i = 0; i < 8; i++) {
                float t = sre[i];
                sre[i] = fmaf(are[i], t, fmaf(-aim[i], sim[i], u));
                sim[i] = fmaf(aim[i], t, are[i] * sim[i]);
                acc = fmaf(cre[i], sre[i], acc);
                acc = fmaf(-cim[i], sim[i], acc);
            }
            acc += __shfl_xor_sync(0xffffffffu, acc, 1);
            acc += __shfl_xor_sync(0xffffffffu, acc, 2);
            if (r == 0) y_sm[g][l - l0] = acc;
        }
        __syncthreads();
        for (int idx = tid; idx < 32 * 32; idx += 128) {
            int row = idx >> 5, col = idx & 31;
            int l = l0 + col;
            if (l < 250) {
                float u = u_sm[row][l];
                float v = y_sm[row][col] + Dv[h0 + row] * u;
                // tanh-approx GELU (jax.nn.gelu default)
                float t = 0.7978845608028654f * (v + 0.044715f * v * v * v);
                g_y[ybase + row * 250 + l] = 0.5f * v * (1.f + tanhf(t));
            }
        }
        __syncthreads();
    }
}

// ---------------- z = ow @ y + ob, then GLU -> g  (per seq) ------------------
// block: 128 threads; thread o holds rows o and o+128 (GLU pair in-register).
__global__ void gemm_ow(const float* __restrict__ ow, const float* __restrict__ ob)
{
    __shared__ float ytile[16][33];
    __shared__ float gsm[128][33];
    int seq = blockIdx.x;
    int l0  = blockIdx.y * 32;
    int o   = threadIdx.x;
    float acc1[32], acc2[32];
    float b1 = ob[o], b2v = ob[o + 128];
    #pragma unroll
    for (int j = 0; j < 32; j++) { acc1[j] = b1; acc2[j] = b2v; }
    int yb = seq * SEQ_STRIDE;
    for (int hc = 0; hc < 128; hc += 16) {
        for (int idx = o; idx < 16 * 32; idx += 128) {
            int i = idx >> 5, j = idx & 31;
            int l = l0 + j;
            ytile[i][j] = (l < 250) ? g_y[yb + (hc + i) * 250 + l] : 0.f;
        }
        __syncthreads();
        #pragma unroll
        for (int i = 0; i < 16; i++) {
            float w1 = __ldg(&ow[o * 128 + hc + i]);
            float w2 = __ldg(&ow[(o + 128) * 128 + hc + i]);
            #pragma unroll
            for (int j = 0; j < 32; j++) {
                float v = ytile[i][j];
                acc1[j] = fmaf(w1, v, acc1[j]);
                acc2[j] = fmaf(w2, v, acc2[j]);
            }
        }
        __syncthreads();
    }
    #pragma unroll
    for (int j = 0; j < 32; j++) {
        float s = 1.f / (1.f + expf(-acc2[j]));
        gsm[o][j] = acc1[j] * s;
    }
    __syncthreads();
    for (int idx = o; idx < 128 * 32; idx += 128) {
        int row = idx >> 5, col = idx & 31;
        int l = l0 + col;
        if (l < 250) g_g[yb + row * 250 + l] = gsm[row][col];
    }
}

// --------- b2[r,:] = lw @ g_flat[r,:] + lb over 128-wide flat rows -----------
// block: 128 threads (one output channel each) x 16 rows.
__global__ void gemm_lw(const float* __restrict__ lw, const float* __restrict__ lb)
{
    __shared__ float insm[128 * 16];
    int r0 = blockIdx.x * 16;
    int o  = threadIdx.x;
    for (int idx = o; idx < 16 * 128; idx += 128) {
        int c = idx & 127, row = idx >> 7;
        insm[c * 16 + row] = g_g[(r0 + row) * 128 + c];
    }
    __syncthreads();
    float acc[16];
    float bias = lb[o];
    #pragma unroll
    for (int j = 0; j < 16; j++) acc[j] = bias;
    #pragma unroll 4
    for (int c = 0; c < 128; c++) {
        float w = __ldg(&lw[o * 128 + c]);
        const float4* vp = (const float4*)&insm[c * 16];
        #pragma unroll
        for (int j4 = 0; j4 < 4; j4++) {
            float4 v = vp[j4];
            acc[j4 * 4 + 0] = fmaf(w, v.x, acc[j4 * 4 + 0]);
            acc[j4 * 4 + 1] = fmaf(w, v.y, acc[j4 * 4 + 1]);
            acc[j4 * 4 + 2] = fmaf(w, v.z, acc[j4 * 4 + 2]);
            acc[j4 * 4 + 3] = fmaf(w, v.w, acc[j4 * 4 + 3]);
        }
    }
    #pragma unroll
    for (int j = 0; j < 16; j++)
        g_b2[(r0 + j) * 128 + o] = acc[j];
}

// ----------------- GroupNorm stats: two-stage deterministic ------------------
__global__ void red1()
{
    int b = blockIdx.x, blk = blockIdx.y;
    int start = b * PER_B + blk * 62500;
    float s = 0.f, ss = 0.f;
    for (int i = threadIdx.x; i < 62500; i += 256) {
        float v = g_b2[start + i];
        s += v;
        ss = fmaf(v, v, ss);
    }
    __shared__ float sm[256], sm2[256];
    sm[threadIdx.x] = s; sm2[threadIdx.x] = ss;
    __syncthreads();
    for (int st = 128; st > 0; st >>= 1) {
        if (threadIdx.x < st) {
            sm[threadIdx.x]  += sm[threadIdx.x + st];
            sm2[threadIdx.x] += sm2[threadIdx.x + st];
        }
        __syncthreads();
    }
    if (threadIdx.x == 0) {
        g_red[(b * 128 + blk) * 2 + 0] = sm[0];
        g_red[(b * 128 + blk) * 2 + 1] = sm2[0];
    }
}

__global__ void red2()
{
    int b = blockIdx.x;
    __shared__ float sm[128], sm2[128];
    int t = threadIdx.x;
    sm[t]  = g_red[(b * 128 + t) * 2 + 0];
    sm2[t] = g_red[(b * 128 + t) * 2 + 1];
    __syncthreads();
    for (int st = 64; st > 0; st >>= 1) {
        if (t < st) { sm[t] += sm[t + st]; sm2[t] += sm2[t + st]; }
        __syncthreads();
    }
    if (t == 0) {
        float inv = 1.f / (float)PER_B;
        float mu = sm[0] * inv;
        float var = sm2[0] * inv - mu * mu;
        g_stats[b * 2 + 0] = mu;
        g_stats[b * 2 + 1] = rsqrtf(var + 1e-8f);
    }
}

// -------- intra finalize: transpose b2 -> [B,N,K,S], GN, + x  -> g_X1 --------
__global__ void finalize_intra(const float* __restrict__ x,
                               const float* __restrict__ gg,
                               const float* __restrict__ gb)
{
    __shared__ float tile[32][33];
    int bh = blockIdx.x;
    int b = bh >> 7, n = bh & 127;
    int k0 = blockIdx.y * 32, s0 = blockIdx.z * 32;
    int tx = threadIdx.x, ty = threadIdx.y;
    float mu = g_stats[b * 2], istd = g_stats[b * 2 + 1];
    float ga = gg[n] * istd;
    float gbb = gb[n] - mu * ga;
    #pragma unroll
    for (int yy = 0; yy < 32; yy += 8) {
        int s = s0 + ty + yy, k = k0 + tx;
        if (s < 250 && k < 250)
            tile[ty + yy][tx] = g_b2[(b * 250 + s) * SEQ_STRIDE + n * 250 + k];
    }
    __syncthreads();
    #pragma unroll
    for (int yy = 0; yy < 32; yy += 8) {
        int k = k0 + ty + yy, s = s0 + tx;
        if (s < 250 && k < 250) {
            int xi = ((b * 128 + n) * 250 + k) * 250 + s;
            g_X1[xi] = tile[tx][ty + yy] * ga + gbb + x[xi];
        }
    }
}

// ------------- inter finalize: GN + residual (no transpose needed) -----------
__global__ void finalize_inter(const float* __restrict__ gg,
                               const float* __restrict__ gb,
                               float* __restrict__ out)
{
    int idx = blockIdx.x * 256 + threadIdx.x;
    if (idx < TOT) {
        int b = idx / PER_B;
        int rem = idx - b * PER_B;
        int n = rem / 62500;
        int rem2 = rem - n * 62500;
        int k = rem2 / 250;
        int s = rem2 - k * 250;
        float v = g_b2[(b * 250 + k) * SEQ_STRIDE + n * 250 + s];
        float mu = g_stats[b * 2], istd = g_stats[b * 2 + 1];
        out[idx] = (v - mu) * istd * gg[n] + gb[n] + g_X1[idx];
    }
}

// ------------------------------- launcher ------------------------------------
extern "C" void kernel_launch(void* const* d_in, const int* in_sizes, int n_in,
                              void* d_out, int out_size)
{
    const float* x = (const float*)d_in[0];
    // per-path params: log_dt, logA_re, A_im, C_re, C_im, D, ow, ob, lw, lb, gg, gb
    const float* P[2][12];
    for (int p = 0; p < 2; p++)
        for (int i = 0; i < 12; i++)
            P[p][i] = (const float*)d_in[1 + p * 12 + i];
    float* out = (float*)d_out;

    prep_params<<<128, 32>>>(P[0][0], P[0][1], P[0][2], P[0][3], P[0][4], 0);
    prep_params<<<128, 32>>>(P[1][0], P[1][1], P[1][2], P[1][3], P[1][4], 1);

    // ---- intra path ----
    transpose_in<<<dim3(512, 8, 8), dim3(32, 8)>>>(x);
    conv_s4<<<dim3(NSEQ, 4), 128>>>(0, P[0][5]);
    gemm_ow<<<dim3(NSEQ, 8), 128>>>(P[0][6], P[0][7]);
    gemm_lw<<<15625, 128>>>(P[0][8], P[0][9]);
    red1<<<dim3(4, 128), 256>>>();
    red2<<<4, 128>>>();
    finalize_intra<<<dim3(512, 8, 8), dim3(32, 8)>>>(x, P[0][10], P[0][11]);

    // ---- inter path ----
    conv_s4<<<dim3(NSEQ, 4), 128>>>(1, P[1][5]);
    gemm_ow<<<dim3(NSEQ, 8), 128>>>(P[1][6], P[1][7]);
    gemm_lw<<<15625, 128>>>(P[1][8], P[1][9]);
    red1<<<dim3(4, 128), 256>>>();
    red2<<<4, 128>>>();
    finalize_inter<<<125000, 256>>>(P[1][10], P[1][11], out);
}

// round 2
// speedup vs baseline: 1.6158x; 1.6158x over previous
#include <cuda_runtime.h>
#include <math.h>

// Problem constants
#define Bb 4
#define Nn 128
#define Kk 250
#define Ss 250
#define Mm 32
#define NSEQ 1000
#define LSEQ 250
#define SEQ_STRIDE 32000
#define TOT 32000000
#define PER_B 8000000
#define NM 4096

__device__ float g_uT[TOT];
__device__ float g_y[TOT];
__device__ float g_g[TOT];
__device__ float g_b2[TOT];
__device__ float g_X1[TOT];
__device__ float g_P[2 * 4 * NM];
__device__ float g_red[Bb * 128 * 2];
__device__ float g_stats[Bb * 2];

// ---------------- parameter prep: a = exp(dt*A), C' = 2*C*(a-1)/A ------------
__global__ void prep_params(const float* __restrict__ log_dt,
                            const float* __restrict__ logA_re,
                            const float* __restrict__ A_im,
                            const float* __restrict__ C_re,
                            const float* __restrict__ C_im,
                            int path)
{
    int h = blockIdx.x;
    int m = threadIdx.x;
    float dt  = expf(log_dt[h]);
    float Are = -expf(logA_re[h * Mm + m]);
    float Aim = A_im[h * Mm + m];
    float dre = dt * Are, dim = dt * Aim;
    float e   = expf(dre);
    float are = e * cosf(dim);
    float aim = e * sinf(dim);
    float nre = are - 1.0f, nim = aim;
    float d2  = Are * Are + Aim * Aim;
    float qre = (nre * Are + nim * Aim) / d2;
    float qim = (nim * Are - nre * Aim) / d2;
    float cr  = C_re[h * Mm + m], ci = C_im[h * Mm + m];
    float c2r = 2.0f * (cr * qre - ci * qim);
    float c2i = 2.0f * (cr * qim + ci * qre);
    int base = path * 4 * NM + h * Mm + m;
    g_P[base + 0 * NM] = are;
    g_P[base + 1 * NM] = aim;
    g_P[base + 2 * NM] = c2r;
    g_P[base + 3 * NM] = c2i;
}

// -------- transpose x [B,N,K,S] -> g_uT [(b*S+s)][h][k] ----------------------
__global__ void transpose_in(const float* __restrict__ x)
{
    __shared__ float tile[32][33];
    int bh = blockIdx.x;
    int b = bh >> 7, h = bh & 127;
    int k0 = blockIdx.y * 32, s0 = blockIdx.z * 32;
    int tx = threadIdx.x, ty = threadIdx.y;
    const float* xin = x + ((b * 128 + h) * 250) * 250;
    #pragma unroll
    for (int yy = 0; yy < 32; yy += 8) {
        int k = k0 + ty + yy, s = s0 + tx;
        if (k < 250 && s < 250)
            tile[ty + yy][tx] = xin[k * 250 + s];
    }
    __syncthreads();
    #pragma unroll
    for (int yy = 0; yy < 32; yy += 8) {
        int s = s0 + ty + yy, k = k0 + tx;
        if (k < 250 && s < 250)
            g_uT[(b * 250 + s) * SEQ_STRIDE + h * 250 + k] = tile[tx][ty + yy];
    }
}

// ------------- S4D conv as complex mode recurrence + D*u + GELU --------------
// 256 threads = 32 (seq,h) groups of 8 lanes; 4 modes per lane.
__global__ void conv_s4(int path, const float* __restrict__ Dv)
{
    __shared__ float u_sm[32][250];
    __shared__ float y_sm[32][32];
    int seq = blockIdx.x;
    int h0  = blockIdx.y * 32;
    int tid = threadIdx.x;

    const float* src;
    int base, s_h;
    if (path == 0) {
        src = g_uT;
        base = seq * SEQ_STRIDE;
        s_h = 250;
    } else {
        src = g_X1;
        int b = seq / 250, k = seq - b * 250;
        base = b * PER_B + k * 250;
        s_h = 62500;
    }

    for (int idx = tid; idx < 32 * 250; idx += 256) {
        int h = idx / 250, l = idx - h * 250;
        u_sm[h][l] = src[base + (h0 + h) * s_h + l];
    }
    __syncthreads();

    int g = tid >> 3, r = tid & 7;
    int pb = path * 4 * NM + (h0 + g) * Mm + r * 4;
    float are[4], aim[4], cre[4], cim[4], sre[4], sim[4];
    #pragma unroll
    for (int i = 0; i < 4; i++) {
        are[i] = g_P[pb + i];
        aim[i] = g_P[pb + NM + i];
        cre[i] = g_P[pb + 2 * NM + i];
        cim[i] = g_P[pb + 3 * NM + i];
        sre[i] = 0.f; sim[i] = 0.f;
    }

    int ybase = seq * SEQ_STRIDE + h0 * 250;
    for (int l0 = 0; l0 < 250; l0 += 32) {
        int lend = min(l0 + 32, 250);
        for (int l = l0; l < lend; l++) {
            float u = u_sm[g][l];
            float acc = 0.f;
            #pragma unroll
            for (int i = 0; i < 4; i++) {
                float t = sre[i];
                sre[i] = fmaf(are[i], t, fmaf(-aim[i], sim[i], u));
                sim[i] = fmaf(aim[i], t, are[i] * sim[i]);
                acc = fmaf(cre[i], sre[i], acc);
                acc = fmaf(-cim[i], sim[i], acc);
            }
            acc += __shfl_xor_sync(0xffffffffu, acc, 1);
            acc += __shfl_xor_sync(0xffffffffu, acc, 2);
            acc += __shfl_xor_sync(0xffffffffu, acc, 4);
            if (r == 0) y_sm[g][l - l0] = acc;
        }
        __syncthreads();
        for (int idx = tid; idx < 32 * 32; idx += 256) {
            int row = idx >> 5, col = idx & 31;
            int l = l0 + col;
            if (l < 250) {
                float u = u_sm[row][l];
                float v = y_sm[row][col] + Dv[h0 + row] * u;
                float t = 0.7978845608028654f * (v + 0.044715f * v * v * v);
                g_y[ybase + row * 250 + l] = 0.5f * v * (1.f + tanhf(t));
            }
        }
        __syncthreads();
    }
}

// ---------------- z = ow @ y + ob, then GLU -> g  (per seq) ------------------
// 128 threads; thread o holds rows o and o+128. Weights staged in padded smem.
__global__ void gemm_ow(const float* __restrict__ ow, const float* __restrict__ ob)
{
    __shared__ float ow_sm[256 * 17];   // rows 0..255 x 16 cols (pad 17)
    __shared__ float ytile[16][33];
    __shared__ float gsm[128][33];
    int seq = blockIdx.x;
    int l0  = blockIdx.y * 32;
    int o   = threadIdx.x;
    float acc1[32], acc2[32];
    float b1 = ob[o], b2v = ob[o + 128];
    #pragma unroll
    for (int j = 0; j < 32; j++) { acc1[j] = b1; acc2[j] = b2v; }
    int yb = seq * SEQ_STRIDE;
    for (int hc = 0; hc < 128; hc += 16) {
        // stage weight chunk (coalesced 64B rows)
        for (int idx = o; idx < 256 * 16; idx += 128) {
            int row = idx >> 4, i = idx & 15;
            ow_sm[row * 17 + i] = ow[row * 128 + hc + i];
        }
        for (int idx = o; idx < 16 * 32; idx += 128) {
            int i = idx >> 5, j = idx & 31;
            int l = l0 + j;
            ytile[i][j] = (l < 250) ? g_y[yb + (hc + i) * 250 + l] : 0.f;
        }
        __syncthreads();
        #pragma unroll
        for (int i = 0; i < 16; i++) {
            float w1 = ow_sm[o * 17 + i];
            float w2 = ow_sm[(o + 128) * 17 + i];
            #pragma unroll
            for (int j = 0; j < 32; j++) {
                float v = ytile[i][j];
                acc1[j] = fmaf(w1, v, acc1[j]);
                acc2[j] = fmaf(w2, v, acc2[j]);
            }
        }
        __syncthreads();
    }
    #pragma unroll
    for (int j = 0; j < 32; j++) {
        float s = 1.f / (1.f + expf(-acc2[j]));
        gsm[o][j] = acc1[j] * s;
    }
    __syncthreads();
    for (int idx = o; idx < 128 * 32; idx += 128) {
        int row = idx >> 5, col = idx & 31;
        int l = l0 + col;
        if (l < 250) g_g[yb + row * 250 + l] = gsm[row][col];
    }
}

// --------- b2[r,:] = lw @ g_flat[r,:] + lb over 128-wide flat rows -----------
// 128 threads (one output channel each) x 32 rows; weights chunked in smem.
__global__ void gemm_lw(const float* __restrict__ lw, const float* __restrict__ lb)
{
    __shared__ float lw_sm[128 * 33];   // 128 o x 32 c (pad 33)
    __shared__ float in_sm[32][32];     // [c][row]
    int r0 = blockIdx.x * 32;
    int o  = threadIdx.x;
    float acc[32];
    float bias = lb[o];
    #pragma unroll
    for (int j = 0; j < 32; j++) acc[j] = bias;

    for (int c0 = 0; c0 < 128; c0 += 32) {
        for (int idx = o; idx < 128 * 32; idx += 128) {
            int row = idx >> 5, c = idx & 31;
            lw_sm[row * 33 + c] = lw[row * 128 + c0 + c];
        }
        for (int idx = o; idx < 32 * 32; idx += 128) {
            int row = idx >> 5, c = idx & 31;
            in_sm[c][row] = g_g[(r0 + row) * 128 + c0 + c];
        }
        __syncthreads();
        #pragma unroll 8
        for (int c = 0; c < 32; c++) {
            float w = lw_sm[o * 33 + c];
            const float4* vp = (const float4*)&in_sm[c][0];
            #pragma unroll
            for (int j4 = 0; j4 < 8; j4++) {
                float4 v = vp[j4];
                acc[j4 * 4 + 0] = fmaf(w, v.x, acc[j4 * 4 + 0]);
                acc[j4 * 4 + 1] = fmaf(w, v.y, acc[j4 * 4 + 1]);
                acc[j4 * 4 + 2] = fmaf(w, v.z, acc[j4 * 4 + 2]);
                acc[j4 * 4 + 3] = fmaf(w, v.w, acc[j4 * 4 + 3]);
            }
        }
        __syncthreads();
    }
    #pragma unroll
    for (int j = 0; j < 32; j++)
        g_b2[(r0 + j) * 128 + o] = acc[j];
}

// ----------------- GroupNorm stats: two-stage deterministic ------------------
__global__ void red1()
{
    int b = blockIdx.x, blk = blockIdx.y;
    int start = b * PER_B + blk * 62500;
    float s = 0.f, ss = 0.f;
    for (int i = threadIdx.x; i < 62500; i += 256) {
        float v = g_b2[start + i];
        s += v;
        ss = fmaf(v, v, ss);
    }
    __shared__ float sm[256], sm2[256];
    sm[threadIdx.x] = s; sm2[threadIdx.x] = ss;
    __syncthreads();
    for (int st = 128; st > 0; st >>= 1) {
        if (threadIdx.x < st) {
            sm[threadIdx.x]  += sm[threadIdx.x + st];
            sm2[threadIdx.x] += sm2[threadIdx.x + st];
        }
        __syncthreads();
    }
    if (threadIdx.x == 0) {
        g_red[(b * 128 + blk) * 2 + 0] = sm[0];
        g_red[(b * 128 + blk) * 2 + 1] = sm2[0];
    }
}

__global__ void red2()
{
    int b = blockIdx.x;
    __shared__ float sm[128], sm2[128];
    int t = threadIdx.x;
    sm[t]  = g_red[(b * 128 + t) * 2 + 0];
    sm2[t] = g_red[(b * 128 + t) * 2 + 1];
    __syncthreads();
    for (int st = 64; st > 0; st >>= 1) {
        if (t < st) { sm[t] += sm[t + st]; sm2[t] += sm2[t + st]; }
        __syncthreads();
    }
    if (t == 0) {
        float inv = 1.f / (float)PER_B;
        float mu = sm[0] * inv;
        float var = sm2[0] * inv - mu * mu;
        g_stats[b * 2 + 0] = mu;
        g_stats[b * 2 + 1] = rsqrtf(var + 1e-8f);
    }
}

// -------- intra finalize: transpose b2 -> [B,N,K,S], GN, + x  -> g_X1 --------
__global__ void finalize_intra(const float* __restrict__ x,
                               const float* __restrict__ gg,
                               const float* __restrict__ gb)
{
    __shared__ float tile[32][33];
    int bh = blockIdx.x;
    int b = bh >> 7, n = bh & 127;
    int k0 = blockIdx.y * 32, s0 = blockIdx.z * 32;
    int tx = threadIdx.x, ty = threadIdx.y;
    float mu = g_stats[b * 2], istd = g_stats[b * 2 + 1];
    float ga = gg[n] * istd;
    float gbb = gb[n] - mu * ga;
    #pragma unroll
    for (int yy = 0; yy < 32; yy += 8) {
        int s = s0 + ty + yy, k = k0 + tx;
        if (s < 250 && k < 250)
            tile[ty + yy][tx] = g_b2[(b * 250 + s) * SEQ_STRIDE + n * 250 + k];
    }
    __syncthreads();
    #pragma unroll
    for (int yy = 0; yy < 32; yy += 8) {
        int k = k0 + ty + yy, s = s0 + tx;
        if (s < 250 && k < 250) {
            int xi = ((b * 128 + n) * 250 + k) * 250 + s;
            g_X1[xi] = tile[tx][ty + yy] * ga + gbb + x[xi];
        }
    }
}

// ------------- inter finalize: GN + residual ---------------------------------
__global__ void finalize_inter(const float* __restrict__ gg,
                               const float* __restrict__ gb,
                               float* __restrict__ out)
{
    int idx = blockIdx.x * 256 + threadIdx.x;
    if (idx < TOT) {
        int b = idx / PER_B;
        int rem = idx - b * PER_B;
        int n = rem / 62500;
        int rem2 = rem - n * 62500;
        int k = rem2 / 250;
        int s = rem2 - k * 250;
        float v = g_b2[(b * 250 + k) * SEQ_STRIDE + n * 250 + s];
        float mu = g_stats[b * 2], istd = g_stats[b * 2 + 1];
        out[idx] = (v - mu) * istd * gg[n] + gb[n] + g_X1[idx];
    }
}

extern "C" void kernel_launch(void* const* d_in, const int* in_sizes, int n_in,
                              void* d_out, int out_size)
{
    const float* x = (const float*)d_in[0];
    const float* P[2][12];
    for (int p = 0; p < 2; p++)
        for (int i = 0; i < 12; i++)
            P[p][i] = (const float*)d_in[1 + p * 12 + i];
    float* out = (float*)d_out;

    prep_params<<<128, 32>>>(P[0][0], P[0][1], P[0][2], P[0][3], P[0][4], 0);
    prep_params<<<128, 32>>>(P[1][0], P[1][1], P[1][2], P[1][3], P[1][4], 1);

    // ---- intra path ----
    transpose_in<<<dim3(512, 8, 8), dim3(32, 8)>>>(x);
    conv_s4<<<dim3(NSEQ, 4), 256>>>(0, P[0][5]);
    gemm_ow<<<dim3(NSEQ, 8), 128>>>(P[0][6], P[0][7]);
    gemm_lw<<<7813, 128>>>(P[0][8], P[0][9]);
    red1<<<dim3(4, 128), 256>>>();
    red2<<<4, 128>>>();
    finalize_intra<<<dim3(512, 8, 8), dim3(32, 8)>>>(x, P[0][10], P[0][11]);

    // ---- inter path ----
    conv_s4<<<dim3(NSEQ, 4), 256>>>(1, P[1][5]);
    gemm_ow<<<dim3(NSEQ, 8), 128>>>(P[1][6], P[1][7]);
    gemm_lw<<<7813, 128>>>(P[1][8], P[1][9]);
    red1<<<dim3(4, 128), 256>>>();
    red2<<<4, 128>>>();
    finalize_inter<<<125000, 256>>>(P[1][10], P[1][11], out);
}

// round 5
// speedup vs baseline: 2.7337x; 1.6918x over previous
#include <cuda_runtime.h>
#include <stdint.h>
#include <math.h>

// Problem constants
#define Bb 4
#define Nn 128
#define Kk 250
#define Ss 250
#define Mm 32
#define NSEQ 1000
#define LSEQ 250
#define SEQ_STRIDE 32000
#define TOT 32000000
#define PER_B 8000000
#define NM 4096

__device__ float g_uT[TOT];
__device__ float g_y[TOT];
__device__ float g_g[TOT];
__device__ float g_b2[TOT];
__device__ float g_X1[TOT];
__device__ float g_P[2 * 4 * NM];
__device__ float g_red[Bb * 128 * 2];
__device__ float g_stats[Bb * 2];

__device__ __forceinline__ unsigned int f2tf32(float f)
{
    unsigned int u;
    asm("cvt.rna.tf32.f32 %0, %1;" : "=r"(u) : "f"(f));
    return u;
}

__device__ __forceinline__ void mma_tf32(float& c0, float& c1, float& c2, float& c3,
                                         unsigned int ra0, unsigned int ra1,
                                         unsigned int ra2, unsigned int ra3,
                                         unsigned int rb0, unsigned int rb1)
{
    asm volatile("mma.sync.aligned.m16n8k8.row.col.f32.tf32.tf32.f32 "
                 "{%0,%1,%2,%3}, {%4,%5,%6,%7}, {%8,%9}, {%0,%1,%2,%3};"
                 : "+f"(c0), "+f"(c1), "+f"(c2), "+f"(c3)
                 : "r"(ra0), "r"(ra1), "r"(ra2), "r"(ra3), "r"(rb0), "r"(rb1));
}

// ---------------- parameter prep: a = exp(dt*A), C' = 2*C*(a-1)/A ------------
__global__ void prep_params(const float* __restrict__ log_dt,
                            const float* __restrict__ logA_re,
                            const float* __restrict__ A_im,
                            const float* __restrict__ C_re,
                            const float* __restrict__ C_im,
                            int path)
{
    int h = blockIdx.x;
    int m = threadIdx.x;
    float dt  = expf(log_dt[h]);
    float Are = -expf(logA_re[h * Mm + m]);
    float Aim = A_im[h * Mm + m];
    float dre = dt * Are, dim = dt * Aim;
    float e   = expf(dre);
    float vre = e * cosf(dim);
    float vim = e * sinf(dim);
    float nre = vre - 1.0f, nim = vim;
    float d2  = Are * Are + Aim * Aim;
    float qre = (nre * Are + nim * Aim) / d2;
    float qim = (nim * Are - nre * Aim) / d2;
    float cr  = C_re[h * Mm + m], ci = C_im[h * Mm + m];
    float c2r = 2.0f * (cr * qre - ci * qim);
    float c2i = 2.0f * (cr * qim + ci * qre);
    int base = path * 4 * NM + h * Mm + m;
    g_P[base + 0 * NM] = vre;
    g_P[base + 1 * NM] = vim;
    g_P[base + 2 * NM] = c2r;
    g_P[base + 3 * NM] = c2i;
}

// -------- transpose x [B,N,K,S] -> g_uT [(b*S+s)][h][k] ----------------------
__global__ void transpose_in(const float* __restrict__ x)
{
    __shared__ float tile[32][33];
    int bh = blockIdx.x;
    int b = bh >> 7, h = bh & 127;
    int k0 = blockIdx.y * 32, s0 = blockIdx.z * 32;
    int tx = threadIdx.x, ty = threadIdx.y;
    const float* xin = x + ((b * 128 + h) * 250) * 250;
    #pragma unroll
    for (int yy = 0; yy < 32; yy += 8) {
        int k = k0 + ty + yy, s = s0 + tx;
        if (k < 250 && s < 250)
            tile[ty + yy][tx] = xin[k * 250 + s];
    }
    __syncthreads();
    #pragma unroll
    for (int yy = 0; yy < 32; yy += 8) {
        int s = s0 + ty + yy, k = k0 + tx;
        if (k < 250 && s < 250)
            g_uT[(b * 250 + s) * SEQ_STRIDE + h * 250 + k] = tile[tx][ty + yy];
    }
}

// ------------- S4D conv as complex mode recurrence + D*u + GELU --------------
__global__ void conv_s4(int path, const float* __restrict__ Dv)
{
    __shared__ float u_sm[32][250];
    __shared__ float y_sm[32][32];
    int seq = blockIdx.x;
    int h0  = blockIdx.y * 32;
    int tid = threadIdx.x;

    const float* src;
    int base, s_h;
    if (path == 0) {
        src = g_uT;
        base = seq * SEQ_STRIDE;
        s_h = 250;
    } else {
        src = g_X1;
        int b = seq / 250, k = seq - b * 250;
        base = b * PER_B + k * 250;
        s_h = 62500;
    }

    for (int idx = tid; idx < 32 * 250; idx += 256) {
        int h = idx / 250, l = idx - h * 250;
        u_sm[h][l] = src[base + (h0 + h) * s_h + l];
    }
    __syncthreads();

    int g = tid >> 3, r = tid & 7;
    int pb = path * 4 * NM + (h0 + g) * Mm + r * 4;
    float pre[4], pim[4], cre[4], cim[4], sre[4], sim[4];
    #pragma unroll
    for (int i = 0; i < 4; i++) {
        pre[i] = g_P[pb + i];
        pim[i] = g_P[pb + NM + i];
        cre[i] = g_P[pb + 2 * NM + i];
        cim[i] = g_P[pb + 3 * NM + i];
        sre[i] = 0.f; sim[i] = 0.f;
    }

    int ybase = seq * SEQ_STRIDE + h0 * 250;
    for (int l0 = 0; l0 < 250; l0 += 32) {
        int lend = min(l0 + 32, 250);
        for (int l = l0; l < lend; l++) {
            float u = u_sm[g][l];
            float acc = 0.f;
            #pragma unroll
            for (int i = 0; i < 4; i++) {
                float t = sre[i];
                sre[i] = fmaf(pre[i], t, fmaf(-pim[i], sim[i], u));
                sim[i] = fmaf(pim[i], t, pre[i] * sim[i]);
                acc = fmaf(cre[i], sre[i], acc);
                acc = fmaf(-cim[i], sim[i], acc);
            }
            acc += __shfl_xor_sync(0xffffffffu, acc, 1);
            acc += __shfl_xor_sync(0xffffffffu, acc, 2);
            acc += __shfl_xor_sync(0xffffffffu, acc, 4);
            if (r == 0) y_sm[g][l - l0] = acc;
        }
        __syncthreads();
        for (int idx = tid; idx < 32 * 32; idx += 256) {
            int row = idx >> 5, col = idx & 31;
            int l = l0 + col;
            if (l < 250) {
                float u = u_sm[row][l];
                float v = y_sm[row][col] + Dv[h0 + row] * u;
                float t = 0.7978845608028654f * (v + 0.044715f * v * v * v);
                g_y[ybase + row * 250 + l] = 0.5f * v * (1.f + tanhf(t));
            }
        }
        __syncthreads();
    }
}

// --------------- GEMM1 (tf32 mma): z = ow@y + ob, GLU -> g -------------------
// 256 threads / 8 warps. Block = (seq, 64-token tile).
// Warp w: output rows {16w..16w+15} and {128+16w..128+16w+15} (GLU pair in-reg).
__global__ void gemm_ow_mma(const float* __restrict__ ow, const float* __restrict__ ob)
{
    __shared__ char sm_raw[46080];
    unsigned int* owc = (unsigned int*)sm_raw;            // [256][36]
    unsigned int* ysm = (unsigned int*)(sm_raw + 36864);  // [32][72]
    float*        gout = (float*)sm_raw;                  // [128][66] (reused)

    int seq = blockIdx.x;
    int l0  = blockIdx.y * 64;
    int tid = threadIdx.x;
    int w   = tid >> 5;
    int lane = tid & 31;
    int g = lane >> 2, tg = lane & 3;
    int yb = seq * SEQ_STRIDE;

    float c[2][8][4];
    #pragma unroll
    for (int m = 0; m < 2; m++)
        #pragma unroll
        for (int nt = 0; nt < 8; nt++)
            #pragma unroll
            for (int i = 0; i < 4; i++)
                c[m][nt][i] = 0.f;

    for (int kc = 0; kc < 128; kc += 32) {
        for (int idx = tid; idx < 256 * 32; idx += 256) {
            int row = idx >> 5, kk = idx & 31;
            owc[row * 36 + kk] = f2tf32(ow[row * 128 + kc + kk]);
        }
        for (int idx = tid; idx < 32 * 64; idx += 256) {
            int kk = idx >> 6, l = idx & 63;
            float v = (l0 + l < 250) ? g_y[yb + (kc + kk) * 250 + l0 + l] : 0.f;
            ysm[kk * 72 + l] = f2tf32(v);
        }
        __syncthreads();
        #pragma unroll
        for (int ks = 0; ks < 4; ks++) {
            int kb = ks * 8;
            unsigned int fa0[2], fa1[2], fa2[2], fa3[2];
            #pragma unroll
            for (int m = 0; m < 2; m++) {
                int row = m * 128 + 16 * w + g;
                fa0[m] = owc[row * 36 + kb + tg];
                fa1[m] = owc[(row + 8) * 36 + kb + tg];
                fa2[m] = owc[row * 36 + kb + tg + 4];
                fa3[m] = owc[(row + 8) * 36 + kb + tg + 4];
            }
            #pragma unroll
            for (int nt = 0; nt < 8; nt++) {
                unsigned int fb0 = ysm[(kb + tg) * 72 + nt * 8 + g];
                unsigned int fb1 = ysm[(kb + tg + 4) * 72 + nt * 8 + g];
                #pragma unroll
                for (int m = 0; m < 2; m++)
                    mma_tf32(c[m][nt][0], c[m][nt][1], c[m][nt][2], c[m][nt][3],
                             fa0[m], fa1[m], fa2[m], fa3[m], fb0, fb1);
            }
        }
        __syncthreads();
    }

    float ba0 = ob[16 * w + g],        ba8 = ob[16 * w + g + 8];
    float bb0 = ob[128 + 16 * w + g],  bb8 = ob[128 + 16 * w + g + 8];
    #pragma unroll
    for (int nt = 0; nt < 8; nt++) {
        float z10 = c[0][nt][0] + ba0, z11 = c[0][nt][1] + ba0;
        float z12 = c[0][nt][2] + ba8, z13 = c[0][nt][3] + ba8;
        float z20 = c[1][nt][0] + bb0, z21 = c[1][nt][1] + bb0;
        float z22 = c[1][nt][2] + bb8, z23 = c[1][nt][3] + bb8;
        int col = nt * 8 + 2 * tg;
        gout[(16 * w + g) * 66 + col]     = z10 / (1.f + expf(-z20));
        gout[(16 * w + g) * 66 + col + 1] = z11 / (1.f + expf(-z21));
        gout[(16 * w + g + 8) * 66 + col]     = z12 / (1.f + expf(-z22));
        gout[(16 * w + g + 8) * 66 + col + 1] = z13 / (1.f + expf(-z23));
    }
    __syncthreads();
    for (int idx = tid; idx < 128 * 64; idx += 256) {
        int row = idx >> 6, l = idx & 63;
        if (l0 + l < 250)
            g_g[yb + row * 250 + l0 + l] = gout[row * 66 + l];
    }
}

// ------------ GEMM2 (tf32 mma): b2_flat = lw @ g_flat + lb -------------------
// 256 threads / 8 warps. Block = (seq, 64-flat-row tile). Warp w: O rows 16w..16w+15.
__global__ void gemm_lw_mma(const float* __restrict__ lw, const float* __restrict__ lb)
{
    __shared__ char sm_raw[33792];
    unsigned int* lsm = (unsigned int*)sm_raw;            // [128][36]
    unsigned int* gsm = (unsigned int*)(sm_raw + 18432);  // [64][40]
    float*        outsm = (float*)sm_raw;                 // [64][132] (reused)

    int seq = blockIdx.x;
    int r0  = blockIdx.y * 64;
    int tid = threadIdx.x;
    int w   = tid >> 5;
    int lane = tid & 31;
    int g = lane >> 2, tg = lane & 3;
    long long gbase = (long long)seq * SEQ_STRIDE;

    float c[8][4];
    #pragma unroll
    for (int nt = 0; nt < 8; nt++)
        #pragma unroll
        for (int i = 0; i < 4; i++)
            c[nt][i] = 0.f;

    for (int kc = 0; kc < 128; kc += 32) {
        for (int idx = tid; idx < 128 * 32; idx += 256) {
            int row = idx >> 5, kk = idx & 31;
            lsm[row * 36 + kk] = f2tf32(lw[row * 128 + kc + kk]);
        }
        for (int idx = tid; idx < 64 * 32; idx += 256) {
            int row = idx >> 5, kk = idx & 31;
            float v = (r0 + row < 250) ? g_g[gbase + (r0 + row) * 128 + kc + kk] : 0.f;
            gsm[row * 40 + kk] = f2tf32(v);
        }
        __syncthreads();
        #pragma unroll
        for (int ks = 0; ks < 4; ks++) {
            int kb = ks * 8;
            int row = 16 * w + g;
            unsigned int fa0 = lsm[row * 36 + kb + tg];
            unsigned int fa1 = lsm[(row + 8) * 36 + kb + tg];
            unsigned int fa2 = lsm[row * 36 + kb + tg + 4];
            unsigned int fa3 = lsm[(row + 8) * 36 + kb + tg + 4];
            #pragma unroll
            for (int nt = 0; nt < 8; nt++) {
                unsigned int fb0 = gsm[(nt * 8 + g) * 40 + kb + tg];
                unsigned int fb1 = gsm[(nt * 8 + g) * 40 + kb + tg + 4];
                mma_tf32(c[nt][0], c[nt][1], c[nt][2], c[nt][3],
                         fa0, fa1, fa2, fa3, fb0, fb1);
            }
        }
        __syncthreads();
    }

    float bv0 = lb[16 * w + g], bv8 = lb[16 * w + g + 8];
    #pragma unroll
    for (int nt = 0; nt < 8; nt++) {
        int trow = nt * 8 + 2 * tg;
        int ocol = 16 * w + g;
        outsm[trow * 132 + ocol]           = c[nt][0] + bv0;
        outsm[(trow + 1) * 132 + ocol]     = c[nt][1] + bv0;
        outsm[trow * 132 + ocol + 8]       = c[nt][2] + bv8;
        outsm[(trow + 1) * 132 + ocol + 8] = c[nt][3] + bv8;
    }
    __syncthreads();
    for (int idx = tid; idx < 64 * 128; idx += 256) {
        int row = idx >> 7, o = idx & 127;
        if (r0 + row < 250)
            g_b2[gbase + (r0 + row) * 128 + o] = outsm[row * 132 + o];
    }
}

// ----------------- GroupNorm stats: two-stage deterministic ------------------
__global__ void red1()
{
    int b = blockIdx.x, blk = blockIdx.y;
    int start = b * PER_B + blk * 62500;
    float s = 0.f, ss = 0.f;
    for (int i = threadIdx.x; i < 62500; i += 256) {
        float v = g_b2[start + i];
        s += v;
        ss = fmaf(v, v, ss);
    }
    __shared__ float sm[256], sm2[256];
    sm[threadIdx.x] = s; sm2[threadIdx.x] = ss;
    __syncthreads();
    for (int st = 128; st > 0; st >>= 1) {
        if (threadIdx.x < st) {
            sm[threadIdx.x]  += sm[threadIdx.x + st];
            sm2[threadIdx.x] += sm2[threadIdx.x + st];
        }
        __syncthreads();
    }
    if (threadIdx.x == 0) {
        g_red[(b * 128 + blk) * 2 + 0] = sm[0];
        g_red[(b * 128 + blk) * 2 + 1] = sm2[0];
    }
}

__global__ void red2()
{
    int b = blockIdx.x;
    __shared__ float sm[128], sm2[128];
    int t = threadIdx.x;
    sm[t]  = g_red[(b * 128 + t) * 2 + 0];
    sm2[t] = g_red[(b * 128 + t) * 2 + 1];
    __syncthreads();
    for (int st = 64; st > 0; st >>= 1) {
        if (t < st) { sm[t] += sm[t + st]; sm2[t] += sm2[t + st]; }
        __syncthreads();
    }
    if (t == 0) {
        float inv = 1.f / (float)PER_B;
        float mu = sm[0] * inv;
        float var = sm2[0] * inv - mu * mu;
        g_stats[b * 2 + 0] = mu;
        g_stats[b * 2 + 1] = rsqrtf(var + 1e-8f);
    }
}

// -------- intra finalize: transpose b2 -> [B,N,K,S], GN, + x  -> g_X1 --------
__global__ void finalize_intra(const float* __restrict__ x,
                               const float* __restrict__ gg,
                               const float* __restrict__ gb)
{
    __shared__ float tile[32][33];
    int bh = blockIdx.x;
    int b = bh >> 7, n = bh & 127;
    int k0 = blockIdx.y * 32, s0 = blockIdx.z * 32;
    int tx = threadIdx.x, ty = threadIdx.y;
    float mu = g_stats[b * 2], istd = g_stats[b * 2 + 1];
    float ga = gg[n] * istd;
    float gbb = gb[n] - mu * ga;
    #pragma unroll
    for (int yy = 0; yy < 32; yy += 8) {
        int s = s0 + ty + yy, k = k0 + tx;
        if (s < 250 && k < 250)
            tile[ty + yy][tx] = g_b2[(b * 250 + s) * SEQ_STRIDE + n * 250 + k];
    }
    __syncthreads();
    #pragma unroll
    for (int yy = 0; yy < 32; yy += 8) {
        int k = k0 + ty + yy, s = s0 + tx;
        if (s < 250 && k < 250) {
            int xi = ((b * 128 + n) * 250 + k) * 250 + s;
            g_X1[xi] = tile[tx][ty + yy] * ga + gbb + x[xi];
        }
    }
}

// ------------- inter finalize: GN + residual ---------------------------------
__global__ void finalize_inter(const float* __restrict__ gg,
                               const float* __restrict__ gb,
                               float* __restrict__ out)
{
    int idx = blockIdx.x * 256 + threadIdx.x;
    if (idx < TOT) {
        int b = idx / PER_B;
        int rem = idx - b * PER_B;
        int n = rem / 62500;
        int rem2 = rem - n * 62500;
        int k = rem2 / 250;
        int s = rem2 - k * 250;
        float v = g_b2[(b * 250 + k) * SEQ_STRIDE + n * 250 + s];
        float mu = g_stats[b * 2], istd = g_stats[b * 2 + 1];
        out[idx] = (v - mu) * istd * gg[n] + gb[n] + g_X1[idx];
    }
}

extern "C" void kernel_launch(void* const* d_in, const int* in_sizes, int n_in,
                              void* d_out, int out_size)
{
    const float* x = (const float*)d_in[0];
    const float* P[2][12];
    for (int p = 0; p < 2; p++)
        for (int i = 0; i < 12; i++)
            P[p][i] = (const float*)d_in[1 + p * 12 + i];
    float* out = (float*)d_out;

    prep_params<<<128, 32>>>(P[0][0], P[0][1], P[0][2], P[0][3], P[0][4], 0);
    prep_params<<<128, 32>>>(P[1][0], P[1][1], P[1][2], P[1][3], P[1][4], 1);

    // ---- intra path ----
    transpose_in<<<dim3(512, 8, 8), dim3(32, 8)>>>(x);
    conv_s4<<<dim3(NSEQ, 4), 256>>>(0, P[0][5]);
    gemm_ow_mma<<<dim3(NSEQ, 4), 256>>>(P[0][6], P[0][7]);
    gemm_lw_mma<<<dim3(NSEQ, 4), 256>>>(P[0][8], P[0][9]);
    red1<<<dim3(4, 128), 256>>>();
    red2<<<4, 128>>>();
    finalize_intra<<<dim3(512, 8, 8), dim3(32, 8)>>>(x, P[0][10], P[0][11]);

    // ---- inter path ----
    conv_s4<<<dim3(NSEQ, 4), 256>>>(1, P[1][5]);
    gemm_ow_mma<<<dim3(NSEQ, 4), 256>>>(P[1][6], P[1][7]);
    gemm_lw_mma<<<dim3(NSEQ, 4), 256>>>(P[1][8], P[1][9]);
    red1<<<dim3(4, 128), 256>>>();
    red2<<<4, 128>>>();
    finalize_inter<<<125000, 256>>>(P[1][10], P[1][11], out);
}

// round 6
// speedup vs baseline: 3.3745x; 1.2344x over previous
#include <cuda_runtime.h>
#include <stdint.h>
#include <math.h>

// Problem constants
#define Bb 4
#define Nn 128
#define Kk 250
#define Ss 250
#define Mm 32
#define NSEQ 1000
#define LSEQ 250
#define SEQ_STRIDE 32000
#define TOT 32000000
#define PER_B 8000000
#define NM 4096

__device__ float g_uT[TOT];
__device__ float g_y[TOT];
__device__ float g_g[TOT];
__device__ float g_b2[TOT];
__device__ float g_X1[TOT];
__device__ float g_P[2 * 6 * NM];           // planes: a_re,a_im,c2r,c2i,dre,dim
__device__ float g_kern[2 * 128 * 384];     // [path][h][128 pad zeros + 250 taps + 6 pad]
__device__ float g_redl[4000 * 2];
__device__ float g_stats[Bb * 2];

__device__ __forceinline__ unsigned int f2tf32(float f)
{
    unsigned int u;
    asm("cvt.rna.tf32.f32 %0, %1;" : "=r"(u) : "f"(f));
    return u;
}

__device__ __forceinline__ void mma_tf32(float& c0, float& c1, float& c2, float& c3,
                                         unsigned int fa0, unsigned int fa1,
                                         unsigned int fa2, unsigned int fa3,
                                         unsigned int fb0, unsigned int fb1)
{
    asm volatile("mma.sync.aligned.m16n8k8.row.col.f32.tf32.tf32.f32 "
                 "{%0,%1,%2,%3}, {%4,%5,%6,%7}, {%8,%9}, {%0,%1,%2,%3};"
                 : "+f"(c0), "+f"(c1), "+f"(c2), "+f"(c3)
                 : "r"(fa0), "r"(fa1), "r"(fa2), "r"(fa3), "r"(fb0), "r"(fb1));
}

// ---------------- parameter prep: a = exp(dt*A), C' = 2*C*(a-1)/A ------------
__global__ void prep_params(const float* __restrict__ log_dt,
                            const float* __restrict__ logA_re,
                            const float* __restrict__ A_im,
                            const float* __restrict__ C_re,
                            const float* __restrict__ C_im,
                            int path)
{
    int h = blockIdx.x;
    int m = threadIdx.x;
    float dt  = expf(log_dt[h]);
    float Are = -expf(logA_re[h * Mm + m]);
    float Aim = A_im[h * Mm + m];
    float dre = dt * Are, dim = dt * Aim;
    float e   = expf(dre);
    float vre = e * cosf(dim);
    float vim = e * sinf(dim);
    float nre = vre - 1.0f, nim = vim;
    float d2  = Are * Are + Aim * Aim;
    float qre = (nre * Are + nim * Aim) / d2;
    float qim = (nim * Are - nre * Aim) / d2;
    float cr  = C_re[h * Mm + m], ci = C_im[h * Mm + m];
    float c2r = 2.0f * (cr * qre - ci * qim);
    float c2i = 2.0f * (cr * qim + ci * qre);
    int base = path * 6 * NM + h * Mm + m;
    g_P[base + 0 * NM] = vre;
    g_P[base + 1 * NM] = vim;
    g_P[base + 2 * NM] = c2r;
    g_P[base + 3 * NM] = c2i;
    g_P[base + 4 * NM] = dre;
    g_P[base + 5 * NM] = dim;
}

// --------- kernel taps: kern[d] = Re(sum_m C'_m a_m^d), d = 0..249 -----------
// block per h; warp w covers l in [32w, 32w+32); lane = mode. exact fp32.
__global__ void kern_gen(int path)
{
    int h = blockIdx.x;
    int tid = threadIdx.x;
    int w = tid >> 5, m = tid & 31;
    int base = path * 6 * NM + h * Mm + m;
    float ar  = g_P[base + 0 * NM];
    float ai  = g_P[base + 1 * NM];
    float c2r = g_P[base + 2 * NM];
    float c2i = g_P[base + 3 * NM];
    float dre = g_P[base + 4 * NM];
    float dim = g_P[base + 5 * NM];
    float l0 = (float)(w * 32);
    float e = expf(l0 * dre);
    float pr = e * cosf(l0 * dim);
    float pi = e * sinf(l0 * dim);
    float* kout = &g_kern[(path * 128 + h) * 384];
    if (tid < 128) kout[tid] = 0.f;
    if (tid < 6)   kout[378 + tid] = 0.f;
    for (int i = 0; i < 32; i++) {
        int l = w * 32 + i;
        float v = fmaf(c2r, pr, -c2i * pi);
        v += __shfl_xor_sync(0xffffffffu, v, 1);
        v += __shfl_xor_sync(0xffffffffu, v, 2);
        v += __shfl_xor_sync(0xffffffffu, v, 4);
        v += __shfl_xor_sync(0xffffffffu, v, 8);
        v += __shfl_xor_sync(0xffffffffu, v, 16);
        if (m == 0 && l < 250) kout[128 + l] = v;
        float t = pr;
        pr = fmaf(ar, t, -ai * pi);
        pi = fmaf(ai, t,  ar * pi);
    }
}

// -------- transpose x [B,N,K,S] -> g_uT [(b*S+s)][h][k] ----------------------
__global__ void transpose_in(const float* __restrict__ x)
{
    __shared__ float tile[32][33];
    int bh = blockIdx.x;
    int b = bh >> 7, h = bh & 127;
    int k0 = blockIdx.y * 32, s0 = blockIdx.z * 32;
    int tx = threadIdx.x, ty = threadIdx.y;
    const float* xin = x + ((b * 128 + h) * 250) * 250;
    #pragma unroll
    for (int yy = 0; yy < 32; yy += 8) {
        int k = k0 + ty + yy, s = s0 + tx;
        if (k < 250 && s < 250)
            tile[ty + yy][tx] = xin[k * 250 + s];
    }
    __syncthreads();
    #pragma unroll
    for (int yy = 0; yy < 32; yy += 8) {
        int s = s0 + ty + yy, k = k0 + tx;
        if (k < 250 && s < 250)
            g_uT[(b * 250 + s) * SEQ_STRIDE + h * 250 + k] = tile[tx][ty + yy];
    }
}

// ------- conv as causal Toeplitz GEMM (tf32 mma) + D*u + GELU, per h ---------
// block: 256 thr / 8 warps. Tile: 128 kout x 64 seq. A-fragments gathered from
// the zero-padded 1-D kernel in smem (causality via pad).
__global__ void conv_gemm(int path, const float* __restrict__ Dv)
{
    __shared__ char smr[33792];
    unsigned int* ksm = (unsigned int*)smr;           // 384 words
    unsigned int* usm = (unsigned int*)(smr + 1536);  // [64 seq][36]
    float*        osm = (float*)smr;                  // [64 seq][132] (reused)

    int h   = blockIdx.x;
    int ko0 = blockIdx.y * 128;
    int s0  = blockIdx.z * 64;
    int tid = threadIdx.x;
    int w = tid >> 5, lane = tid & 31;
    int g = lane >> 2, tg = lane & 3;

    const float* kern = &g_kern[(path * 128 + h) * 384];
    for (int i = tid; i < 384; i += 256) ksm[i] = f2tf32(kern[i]);

    const float* usrc = (path == 0) ? g_uT : g_X1;

    float c[8][4];
    #pragma unroll
    for (int nt = 0; nt < 8; nt++)
        #pragma unroll
        for (int i = 0; i < 4; i++)
            c[nt][i] = 0.f;

    int nch = (blockIdx.y == 0) ? 4 : 8;
    for (int ch = 0; ch < nch; ch++) {
        int ki0 = ch * 32;
        __syncthreads();
        for (int idx = tid; idx < 64 * 32; idx += 256) {
            int row = idx >> 5, kk = idx & 31;
            int seq = s0 + row, l = ki0 + kk;
            float v = 0.f;
            if (seq < 1000 && l < 250) {
                int addr = (path == 0)
                    ? seq * SEQ_STRIDE + h * 250 + l
                    : (seq / 250) * PER_B + h * 62500 + (seq % 250) * 250 + l;
                v = usrc[addr];
            }
            usm[row * 36 + kk] = f2tf32(v);
        }
        __syncthreads();
        #pragma unroll
        for (int ks = 0; ks < 4; ks++) {
            int kb = ks * 8;
            int aoff = 128 + ko0 + 16 * w - ki0 - kb;
            unsigned int fa0 = ksm[aoff + g - tg];
            unsigned int fa1 = ksm[aoff + 8 + g - tg];
            unsigned int fa2 = ksm[aoff + g - tg - 4];
            unsigned int fa3 = ksm[aoff + 8 + g - tg - 4];
            #pragma unroll
            for (int nt = 0; nt < 8; nt++) {
                unsigned int fb0 = usm[(nt * 8 + g) * 36 + kb + tg];
                unsigned int fb1 = usm[(nt * 8 + g) * 36 + kb + tg + 4];
                mma_tf32(c[nt][0], c[nt][1], c[nt][2], c[nt][3],
                         fa0, fa1, fa2, fa3, fb0, fb1);
            }
        }
    }
    __syncthreads();

    // stage C -> osm[seq][kout_local]
    #pragma unroll
    for (int nt = 0; nt < 8; nt++) {
        int col = nt * 8 + 2 * tg;
        int row = 16 * w + g;
        osm[col * 132 + row]           = c[nt][0];
        osm[(col + 1) * 132 + row]     = c[nt][1];
        osm[col * 132 + row + 8]       = c[nt][2];
        osm[(col + 1) * 132 + row + 8] = c[nt][3];
    }
    __syncthreads();

    float Dh = Dv[h];
    for (int idx = tid; idx < 64 * 128; idx += 256) {
        int srow = idx >> 7, k = idx & 127;
        int seq = s0 + srow, kout = ko0 + k;
        if (seq < 1000 && kout < 250) {
            int addr = (path == 0)
                ? seq * SEQ_STRIDE + h * 250 + kout
                : (seq / 250) * PER_B + h * 62500 + (seq % 250) * 250 + kout;
            float u = usrc[addr];
            float v = osm[srow * 132 + k] + Dh * u;
            float t = 0.7978845608028654f * (v + 0.044715f * v * v * v);
            g_y[seq * SEQ_STRIDE + h * 250 + kout] = 0.5f * v * (1.f + tanhf(t));
        }
    }
}

// --------------- GEMM1 (tf32 mma): z = ow@y + ob, GLU -> g -------------------
__global__ void gemm_ow_mma(const float* __restrict__ ow, const float* __restrict__ ob)
{
    __shared__ char sm_raw[46080];
    unsigned int* owc = (unsigned int*)sm_raw;            // [256][36]
    unsigned int* ysm = (unsigned int*)(sm_raw + 36864);  // [32][72]
    float*        gout = (float*)sm_raw;                  // [128][66] (reused)

    int seq = blockIdx.x;
    int l0  = blockIdx.y * 64;
    int tid = threadIdx.x;
    int w   = tid >> 5;
    int lane = tid & 31;
    int g = lane >> 2, tg = lane & 3;
    int yb = seq * SEQ_STRIDE;

    float c[2][8][4];
    #pragma unroll
    for (int m = 0; m < 2; m++)
        #pragma unroll
        for (int nt = 0; nt < 8; nt++)
            #pragma unroll
            for (int i = 0; i < 4; i++)
                c[m][nt][i] = 0.f;

    for (int kc = 0; kc < 128; kc += 32) {
        for (int idx = tid; idx < 256 * 32; idx += 256) {
            int row = idx >> 5, kk = idx & 31;
            owc[row * 36 + kk] = f2tf32(ow[row * 128 + kc + kk]);
        }
        for (int idx = tid; idx < 32 * 64; idx += 256) {
            int kk = idx >> 6, l = idx & 63;
            float v = (l0 + l < 250) ? g_y[yb + (kc + kk) * 250 + l0 + l] : 0.f;
            ysm[kk * 72 + l] = f2tf32(v);
        }
        __syncthreads();
        #pragma unroll
        for (int ks = 0; ks < 4; ks++) {
            int kb = ks * 8;
            unsigned int fa0[2], fa1[2], fa2[2], fa3[2];
            #pragma unroll
            for (int m = 0; m < 2; m++) {
                int row = m * 128 + 16 * w + g;
                fa0[m] = owc[row * 36 + kb + tg];
                fa1[m] = owc[(row + 8) * 36 + kb + tg];
                fa2[m] = owc[row * 36 + kb + tg + 4];
                fa3[m] = owc[(row + 8) * 36 + kb + tg + 4];
            }
            #pragma unroll
            for (int nt = 0; nt < 8; nt++) {
                unsigned int fb0 = ysm[(kb + tg) * 72 + nt * 8 + g];
                unsigned int fb1 = ysm[(kb + tg + 4) * 72 + nt * 8 + g];
                #pragma unroll
                for (int m = 0; m < 2; m++)
                    mma_tf32(c[m][nt][0], c[m][nt][1], c[m][nt][2], c[m][nt][3],
                             fa0[m], fa1[m], fa2[m], fa3[m], fb0, fb1);
            }
        }
        __syncthreads();
    }

    float ba0 = ob[16 * w + g],        ba8 = ob[16 * w + g + 8];
    float bb0 = ob[128 + 16 * w + g],  bb8 = ob[128 + 16 * w + g + 8];
    #pragma unroll
    for (int nt = 0; nt < 8; nt++) {
        float z10 = c[0][nt][0] + ba0, z11 = c[0][nt][1] + ba0;
        float z12 = c[0][nt][2] + ba8, z13 = c[0][nt][3] + ba8;
        float z20 = c[1][nt][0] + bb0, z21 = c[1][nt][1] + bb0;
        float z22 = c[1][nt][2] + bb8, z23 = c[1][nt][3] + bb8;
        int col = nt * 8 + 2 * tg;
        gout[(16 * w + g) * 66 + col]     = z10 / (1.f + expf(-z20));
        gout[(16 * w + g) * 66 + col + 1] = z11 / (1.f + expf(-z21));
        gout[(16 * w + g + 8) * 66 + col]     = z12 / (1.f + expf(-z22));
        gout[(16 * w + g + 8) * 66 + col + 1] = z13 / (1.f + expf(-z23));
    }
    __syncthreads();
    for (int idx = tid; idx < 128 * 64; idx += 256) {
        int row = idx >> 6, l = idx & 63;
        if (l0 + l < 250)
            g_g[yb + row * 250 + l0 + l] = gout[row * 66 + l];
    }
}

// ------------ GEMM2 (tf32 mma): b2_flat = lw @ g_flat + lb + fused GN stats --
__global__ void gemm_lw_mma(const float* __restrict__ lw, const float* __restrict__ lb)
{
    __shared__ char sm_raw[33792];
    __shared__ float rs[256], rs2[256];
    unsigned int* lsm = (unsigned int*)sm_raw;            // [128][36]
    unsigned int* gsm = (unsigned int*)(sm_raw + 18432);  // [64][40]
    float*        outsm = (float*)sm_raw;                 // [64][132] (reused)

    int seq = blockIdx.x;
    int r0  = blockIdx.y * 64;
    int tid = threadIdx.x;
    int w   = tid >> 5;
    int lane = tid & 31;
    int g = lane >> 2, tg = lane & 3;
    long long gbase = (long long)seq * SEQ_STRIDE;

    float c[8][4];
    #pragma unroll
    for (int nt = 0; nt < 8; nt++)
        #pragma unroll
        for (int i = 0; i < 4; i++)
            c[nt][i] = 0.f;

    for (int kc = 0; kc < 128; kc += 32) {
        for (int idx = tid; idx < 128 * 32; idx += 256) {
            int row = idx >> 5, kk = idx & 31;
            lsm[row * 36 + kk] = f2tf32(lw[row * 128 + kc + kk]);
        }
        for (int idx = tid; idx < 64 * 32; idx += 256) {
            int row = idx >> 5, kk = idx & 31;
            float v = (r0 + row < 250) ? g_g[gbase + (r0 + row) * 128 + kc + kk] : 0.f;
            gsm[row * 40 + kk] = f2tf32(v);
        }
        __syncthreads();
        #pragma unroll
        for (int ks = 0; ks < 4; ks++) {
            int kb = ks * 8;
            int row = 16 * w + g;
            unsigned int fa0 = lsm[row * 36 + kb + tg];
            unsigned int fa1 = lsm[(row + 8) * 36 + kb + tg];
            unsigned int fa2 = lsm[row * 36 + kb + tg + 4];
            unsigned int fa3 = lsm[(row + 8) * 36 + kb + tg + 4];
            #pragma unroll
            for (int nt = 0; nt < 8; nt++) {
                unsigned int fb0 = gsm[(nt * 8 + g) * 40 + kb + tg];
                unsigned int fb1 = gsm[(nt * 8 + g) * 40 + kb + tg + 4];
                mma_tf32(c[nt][0], c[nt][1], c[nt][2], c[nt][3],
                         fa0, fa1, fa2, fa3, fb0, fb1);
            }
        }
        __syncthreads();
    }

    float bv0 = lb[16 * w + g], bv8 = lb[16 * w + g + 8];
    #pragma unroll
    for (int nt = 0; nt < 8; nt++) {
        int trow = nt * 8 + 2 * tg;
        int ocol = 16 * w + g;
        outsm[trow * 132 + ocol]           = c[nt][0] + bv0;
        outsm[(trow + 1) * 132 + ocol]     = c[nt][1] + bv0;
        outsm[trow * 132 + ocol + 8]       = c[nt][2] + bv8;
        outsm[(trow + 1) * 132 + ocol + 8] = c[nt][3] + bv8;
    }
    __syncthreads();
    float s_ = 0.f, ss_ = 0.f;
    for (int idx = tid; idx < 64 * 128; idx += 256) {
        int row = idx >> 7, o = idx & 127;
        if (r0 + row < 250) {
            float v = outsm[row * 132 + o];
            g_b2[gbase + (r0 + row) * 128 + o] = v;
            s_ += v;
            ss_ = fmaf(v, v, ss_);
        }
    }
    rs[tid] = s_; rs2[tid] = ss_;
    __syncthreads();
    for (int st = 128; st > 0; st >>= 1) {
        if (tid < st) { rs[tid] += rs[tid + st]; rs2[tid] += rs2[tid + st]; }
        __syncthreads();
    }
    if (tid == 0) {
        int bid = seq * 4 + blockIdx.y;
        g_redl[bid * 2 + 0] = rs[0];
        g_redl[bid * 2 + 1] = rs2[0];
    }
}

// ------------- GroupNorm stats combine (deterministic) -----------------------
__global__ void red_combine()
{
    int b = blockIdx.x;
    int tid = threadIdx.x;
    float s = 0.f, ss = 0.f;
    for (int i = tid; i < 1000; i += 256) {
        s  += g_redl[(b * 1000 + i) * 2 + 0];
        ss += g_redl[(b * 1000 + i) * 2 + 1];
    }
    __shared__ float sm[256], sm2[256];
    sm[tid] = s; sm2[tid] = ss;
    __syncthreads();
    for (int st = 128; st > 0; st >>= 1) {
        if (tid < st) { sm[tid] += sm[tid + st]; sm2[tid] += sm2[tid + st]; }
        __syncthreads();
    }
    if (tid == 0) {
        float inv = 1.f / (float)PER_B;
        float mu = sm[0] * inv;
        float var = sm2[0] * inv - mu * mu;
        g_stats[b * 2 + 0] = mu;
        g_stats[b * 2 + 1] = rsqrtf(var + 1e-8f);
    }
}

// -------- intra finalize: transpose b2 -> [B,N,K,S], GN, + x  -> g_X1 --------
__global__ void finalize_intra(const float* __restrict__ x,
                               const float* __restrict__ gg,
                               const float* __restrict__ gb)
{
    __shared__ float tile[32][33];
    int bh = blockIdx.x;
    int b = bh >> 7, n = bh & 127;
    int k0 = blockIdx.y * 32, s0 = blockIdx.z * 32;
    int tx = threadIdx.x, ty = threadIdx.y;
    float mu = g_stats[b * 2], istd = g_stats[b * 2 + 1];
    float ga = gg[n] * istd;
    float gbb = gb[n] - mu * ga;
    #pragma unroll
    for (int yy = 0; yy < 32; yy += 8) {
        int s = s0 + ty + yy, k = k0 + tx;
        if (s < 250 && k < 250)
            tile[ty + yy][tx] = g_b2[(b * 250 + s) * SEQ_STRIDE + n * 250 + k];
    }
    __syncthreads();
    #pragma unroll
    for (int yy = 0; yy < 32; yy += 8) {
        int k = k0 + ty + yy, s = s0 + tx;
        if (s < 250 && k < 250) {
            int xi = ((b * 128 + n) * 250 + k) * 250 + s;
            g_X1[xi] = tile[tx][ty + yy] * ga + gbb + x[xi];
        }
    }
}

// ------------- inter finalize: GN + residual ---------------------------------
__global__ void finalize_inter(const float* __restrict__ gg,
                               const float* __restrict__ gb,
                               float* __restrict__ out)
{
    int idx = blockIdx.x * 256 + threadIdx.x;
    if (idx < TOT) {
        int b = idx / PER_B;
        int rem = idx - b * PER_B;
        int n = rem / 62500;
        int rem2 = rem - n * 62500;
        int k = rem2 / 250;
        int s = rem2 - k * 250;
        float v = g_b2[(b * 250 + k) * SEQ_STRIDE + n * 250 + s];
        float mu = g_stats[b * 2], istd = g_stats[b * 2 + 1];
        out[idx] = (v - mu) * istd * gg[n] + gb[n] + g_X1[idx];
    }
}

extern "C" void kernel_launch(void* const* d_in, const int* in_sizes, int n_in,
                              void* d_out, int out_size)
{
    const float* x = (const float*)d_in[0];
    const float* P[2][12];
    for (int p = 0; p < 2; p++)
        for (int i = 0; i < 12; i++)
            P[p][i] = (const float*)d_in[1 + p * 12 + i];
    float* out = (float*)d_out;

    prep_params<<<128, 32>>>(P[0][0], P[0][1], P[0][2], P[0][3], P[0][4], 0);
    prep_params<<<128, 32>>>(P[1][0], P[1][1], P[1][2], P[1][3], P[1][4], 1);
    kern_gen<<<128, 256>>>(0);
    kern_gen<<<128, 256>>>(1);

    // ---- intra path ----
    transpose_in<<<dim3(512, 8, 8), dim3(32, 8)>>>(x);
    conv_gemm<<<dim3(128, 2, 16), 256>>>(0, P[0][5]);
    gemm_ow_mma<<<dim3(NSEQ, 4), 256>>>(P[0][6], P[0][7]);
    gemm_lw_mma<<<dim3(NSEQ, 4), 256>>>(P[0][8], P[0][9]);
    red_combine<<<4, 256>>>();
    finalize_intra<<<dim3(512, 8, 8), dim3(32, 8)>>>(x, P[0][10], P[0][11]);

    // ---- inter path ----
    conv_gemm<<<dim3(128, 2, 16), 256>>>(1, P[1][5]);
    gemm_ow_mma<<<dim3(NSEQ, 4), 256>>>(P[1][6], P[1][7]);
    gemm_lw_mma<<<dim3(NSEQ, 4), 256>>>(P[1][8], P[1][9]);
    red_combine<<<4, 256>>>();
    finalize_inter<<<125000, 256>>>(P[1][10], P[1][11], out);
}